// round 15
// baseline (speedup 1.0000x reference)
#include <cuda_runtime.h>
#include <cuda_bf16.h>
#include <cstdint>
#include <cstring>

// ============================================================
// Problem constants
// ============================================================
static constexpr int SEQ   = 80;
static constexpr int EMB   = 100;
static constexpr int BATCH = 4096;
static constexpr int ROWS  = 32;    // batch rows per CTA (recurrent kernel)
static constexpr int NCTA  = 128;   // 4096 / 32
static constexpr int THREADS = 512; // 16 warps: (rt 0..1) x (ug 0..7), M16 x N32

// Z1 = x@W1 + b1, bf16, layout [b*SEQ + t][256]
__device__ __nv_bfloat16 g_z1[(size_t)BATCH * SEQ * 256];

// ============================================================
// Common helpers
// ============================================================
__device__ __forceinline__ uint32_t smem_to_u32(const void* smem_ptr) {
    uint32_t addr;
    asm("{ .reg .u64 tmp; cvta.to.shared.u64 tmp, %1; cvt.u32.u64 %0, tmp; }"
        : "=r"(addr) : "l"(smem_ptr));
    return addr;
}
__device__ __forceinline__ float tanhx(float x) {
    float y;
    asm("tanh.approx.f32 %0, %1;" : "=f"(y) : "f"(x));
    return y;
}
__device__ __forceinline__ float sigx(float x) {
    return fmaf(tanhx(0.5f * x), 0.5f, 0.5f);
}
__device__ __forceinline__ uint32_t packbf2(float lo, float hi) {
    __nv_bfloat162 v = __floats2bfloat162_rn(lo, hi);
    uint32_t u;
    memcpy(&u, &v, 4);
    return u;
}
__device__ __forceinline__ float bfh(uint32_t u, int hi) {
    return __uint_as_float(hi ? (u & 0xffff0000u) : (u << 16));
}
__device__ __forceinline__ void ldsm_x4(uint32_t addr, uint32_t& r0, uint32_t& r1,
                                        uint32_t& r2, uint32_t& r3) {
    asm volatile("ldmatrix.sync.aligned.m8n8.x4.shared.b16 {%0,%1,%2,%3}, [%4];"
                 : "=r"(r0), "=r"(r1), "=r"(r2), "=r"(r3) : "r"(addr));
}
__device__ __forceinline__ void mma16816(float* d, uint32_t a0, uint32_t a1,
                                         uint32_t a2, uint32_t a3,
                                         uint32_t b0, uint32_t b1) {
    asm volatile(
        "mma.sync.aligned.m16n8k16.row.col.f32.bf16.bf16.f32 "
        "{%0,%1,%2,%3}, {%4,%5,%6,%7}, {%8,%9}, {%0,%1,%2,%3};"
        : "+f"(d[0]), "+f"(d[1]), "+f"(d[2]), "+f"(d[3])
        : "r"(a0), "r"(a1), "r"(a2), "r"(a3), "r"(b0), "r"(b1));
}

// ============================================================
// Precompute kernel: Z1 = (emb[tokens] | 1) @ (W1t | b1)  (bf16 out)
// Persistent: 296 CTAs x 256 thr, W1 staged once, M32xN256 tiles (R7 engine)
// ============================================================
static constexpr int P_GRID  = 296;
static constexpr int P_TILES = BATCH * SEQ / 32;              // 10240
static constexpr int P_TPC   = (P_TILES + P_GRID - 1) / P_GRID; // 35
static constexpr int P_OFF_W = 0;        // W1t [256 n][240B]
static constexpr int P_OFF_A = 61440;    // A   [32 m][240B]
static constexpr int P_SMEM  = 61440 + 32 * 240;  // 69120

// M16 x N64 warp tile (R7): acc[gi*8 + nt*4 + rh*2 + uj]
template <int KSTEPS>
__device__ __forceinline__ void do_term64(uint32_t aBase, int aStride,
                                          uint32_t bBase, int bStride,
                                          int RB, int UB, float* acc, int lane) {
    const int lrow = lane & 15;
    const int lk   = (lane >> 4) << 3;
#pragma unroll
    for (int ks = 0; ks < KSTEPS; ks++) {
        uint32_t a0, a1, a2, a3;
        ldsm_x4(aBase + (RB + lrow) * aStride + (ks * 16 + lk) * 2, a0, a1, a2, a3);
#pragma unroll
        for (int gi = 0; gi < 4; gi++) {
            uint32_t r0, r1, r2, r3;
            ldsm_x4(bBase + (gi * 64 + UB + lrow) * bStride + (ks * 16 + lk) * 2,
                    r0, r1, r2, r3);
            mma16816(acc + gi * 8 + 0, a0, a1, a2, a3, r0, r2);
            mma16816(acc + gi * 8 + 4, a0, a1, a2, a3, r1, r3);
        }
    }
}

__global__ void __launch_bounds__(256, 2)
precompute_z1(const int* __restrict__ tokens, const float* __restrict__ emb,
              const float* __restrict__ W1, const float* __restrict__ b1) {
    extern __shared__ char smem[];
    const uint32_t sb = smem_to_u32(smem);
    const int tid  = threadIdx.x;
    const int wid  = tid >> 5;
    const int lane = tid & 31;
    const int rt = wid >> 2, ug = wid & 3;
    const int RB = rt * 16, UB = ug * 16;

    // zero smem (covers k-padding 101..119 of both tiles)
    for (int i = tid * 16; i < P_SMEM; i += 256 * 16)
        *reinterpret_cast<uint4*>(smem + i) = make_uint4(0, 0, 0, 0);
    __syncthreads();
    // stage W1t [n][k] bf16, b1 at k=100
    for (int i = tid; i < 256 * 101; i += 256) {
        int k = i / 256, n = i - k * 256;
        float v = (k < EMB) ? W1[k * 256 + n] : b1[n];
        *reinterpret_cast<__nv_bfloat16*>(smem + P_OFF_W + n * 240 + k * 2) =
            __float2bfloat16(v);
    }
    __syncthreads();

    const int r = tid >> 3, seg = tid & 7;   // 32 rows x 8 threads
    const int g = lane >> 2, tg = lane & 3;

#pragma unroll 1
    for (int i = 0; i < P_TPC; i++) {
        int tile = blockIdx.x * P_TPC + i;
        if (tile >= P_TILES) break;
        int mBase = tile * 32;

        // stage A: 32 gathered embedding rows (bf16), ones col at k=100
        {
            int tok = tokens[mBase + r];
            const float4* ep = reinterpret_cast<const float4*>(emb + (size_t)tok * EMB);
            float4 v0 = ep[seg], v1 = ep[seg + 8], v2 = ep[seg + 16];
            uint32_t ab = sb + P_OFF_A + r * 240;
            uint32_t lo, hi;
            lo = packbf2(v0.x, v0.y); hi = packbf2(v0.z, v0.w);
            asm volatile("st.shared.v2.b32 [%0], {%1,%2};" :: "r"(ab + seg * 8), "r"(lo), "r"(hi));
            lo = packbf2(v1.x, v1.y); hi = packbf2(v1.z, v1.w);
            asm volatile("st.shared.v2.b32 [%0], {%1,%2};" :: "r"(ab + (seg + 8) * 8), "r"(lo), "r"(hi));
            lo = packbf2(v2.x, v2.y); hi = packbf2(v2.z, v2.w);
            asm volatile("st.shared.v2.b32 [%0], {%1,%2};" :: "r"(ab + (seg + 16) * 8), "r"(lo), "r"(hi));
            if (seg == 0) {
                float4 v3 = ep[24];
                lo = packbf2(v3.x, v3.y); hi = packbf2(v3.z, v3.w);
                asm volatile("st.shared.v2.b32 [%0], {%1,%2};" :: "r"(ab + 192), "r"(lo), "r"(hi));
                unsigned short one = 0x3F80;
                asm volatile("st.shared.b16 [%0], %1;" :: "r"(ab + 200), "h"(one));
            }
        }
        __syncthreads();

        float acc[32];
#pragma unroll
        for (int q = 0; q < 32; q++) acc[q] = 0.f;
        do_term64<7>(sb + P_OFF_A, 240, sb + P_OFF_W, 240, RB, UB, acc, lane);

        // store bf16x2 to Z1
#pragma unroll
        for (int gi = 0; gi < 4; gi++)
#pragma unroll
        for (int nt = 0; nt < 2; nt++)
#pragma unroll
        for (int rh = 0; rh < 2; rh++) {
            int m   = mBase + RB + rh * 8 + g;
            int col = gi * 64 + UB + nt * 8 + 2 * tg;
            uint32_t pk = packbf2(acc[gi * 8 + nt * 4 + rh * 2 + 0],
                                  acc[gi * 8 + nt * 4 + rh * 2 + 1]);
            *reinterpret_cast<uint32_t*>(
                reinterpret_cast<char*>(g_z1) + ((size_t)m * 256 + col) * 2) = pk;
        }
        __syncthreads();
    }
}

// ============================================================
// Recurrent kernel smem layout
// ============================================================
static constexpr int SX_U1 = 144;  // k=64
static constexpr int SX_W2 = 176;  // k=80 (h1:64 + bias@64 + pad)
static constexpr int SX_U2 = 144;  // k=64
static constexpr int OFF_U1 = 0;                          // 36864
static constexpr int OFF_W2 = 36864;                      // 45056 -> 81920
static constexpr int OFF_U2 = 81920;                      // 36864 -> 118784
static constexpr int OFF_H1 = 118784;                     // 2 x [32][176] -> 130048
static constexpr int OFF_H2 = 130048;                     // 2 x [32][144] -> 139264
static constexpr int OFF_WD = 139264;                     // 64 f32
static constexpr int OFF_BD = 139520;
static constexpr int OFF_RED = 139536;                    // [32][8] f32
static constexpr int SMEM_TOTAL = OFF_RED + 1024;         // 140560
static constexpr int SMEM_ALLOC = 140672;

// Fused recurrent GEMM terms over shared A = h1 (5 ksteps):
//   acc2 += h1 @ W2t (5 ksteps incl. bias col), acc1 += h1 @ U1t (first 4 ksteps)
template <bool WITH_U1>
__device__ __forceinline__ void do_fused(uint32_t aBase, uint32_t u1Base,
                                         uint32_t w2Base, int RB,
                                         float* acc1, float* acc2, int lane) {
    const int lrow = lane & 15;
    const int lk   = (lane >> 4) << 3;
    const int bq   = lane >> 3;
    const int browL = (bq >> 1) * 64 + (lane & 7);  // + gp*128 + UB added by caller bases
    const int bk   = (bq & 1) << 3;
#pragma unroll
    for (int ks = 0; ks < 5; ks++) {
        uint32_t a0, a1, a2, a3;
        ldsm_x4(aBase + (RB + lrow) * SX_W2 + (ks * 16 + lk) * 2, a0, a1, a2, a3);
#pragma unroll
        for (int gp = 0; gp < 2; gp++) {
            uint32_t r0, r1, r2, r3;
            ldsm_x4(w2Base + (gp * 128 + browL) * SX_W2 + (ks * 16 + bk) * 2,
                    r0, r1, r2, r3);
            mma16816(acc2 + (2 * gp + 0) * 4, a0, a1, a2, a3, r0, r1);
            mma16816(acc2 + (2 * gp + 1) * 4, a0, a1, a2, a3, r2, r3);
        }
        if (WITH_U1 && ks < 4) {
#pragma unroll
            for (int gp = 0; gp < 2; gp++) {
                uint32_t r0, r1, r2, r3;
                ldsm_x4(u1Base + (gp * 128 + browL) * SX_U1 + (ks * 16 + bk) * 2,
                        r0, r1, r2, r3);
                mma16816(acc1 + (2 * gp + 0) * 4, a0, a1, a2, a3, r0, r1);
                mma16816(acc1 + (2 * gp + 1) * 4, a0, a1, a2, a3, r2, r3);
            }
        }
    }
}

// U2 term with register-resident B fragments
__device__ __forceinline__ void do_u2reg(uint32_t aBase, const uint32_t* u2b,
                                         int RB, float* acc2, int lane) {
    const int lrow = lane & 15;
    const int lk   = (lane >> 4) << 3;
#pragma unroll
    for (int ks = 0; ks < 4; ks++) {
        uint32_t a0, a1, a2, a3;
        ldsm_x4(aBase + (RB + lrow) * SX_U2 + (ks * 16 + lk) * 2, a0, a1, a2, a3);
#pragma unroll
        for (int gp = 0; gp < 2; gp++) {
            const uint32_t* b = u2b + (ks * 2 + gp) * 4;
            mma16816(acc2 + (2 * gp + 0) * 4, a0, a1, a2, a3, b[0], b[1]);
            mma16816(acc2 + (2 * gp + 1) * 4, a0, a1, a2, a3, b[2], b[3]);
        }
    }
}

// L2 epilogue (no z): acc -> c/h, h -> smem
__device__ __forceinline__ void epilogue(const float* acc, float* c,
                                         uint32_t hBase, int hStride,
                                         int RB, int UB, int lane,
                                         const float* wd_s, float* pr) {
    const int g = lane >> 2, tg = lane & 3;
#pragma unroll
    for (int rh = 0; rh < 2; rh++) {
        float hv[2];
#pragma unroll
        for (int uj = 0; uj < 2; uj++) {
            const int off = rh * 2 + uj;
            float zi = acc[0 + off], zf = acc[4 + off];
            float zg = acc[8 + off], zo = acc[12 + off];
            float cc = sigx(zf) * c[off] + sigx(zi) * tanhx(zg);
            c[off] = cc;
            hv[uj] = sigx(zo) * tanhx(cc);
        }
        const int row = RB + rh * 8 + g;
        const int u   = UB + 2 * tg;
        uint32_t pk = packbf2(hv[0], hv[1]);
        asm volatile("st.shared.b32 [%0], %1;"
                     :: "r"(hBase + row * hStride + u * 2), "r"(pk));
        if (wd_s) pr[rh] += hv[0] * wd_s[u] + hv[1] * wd_s[u + 1];
    }
}

// L1 epilogue with Z1 added to the gate pre-activations
__device__ __forceinline__ void epilogue_z(const float* acc, const uint32_t* z,
                                           float* c, uint32_t hBase,
                                           int RB, int UB, int lane) {
    const int g = lane >> 2, tg = lane & 3;
#pragma unroll
    for (int rh = 0; rh < 2; rh++) {
        float hv[2];
#pragma unroll
        for (int uj = 0; uj < 2; uj++) {
            const int off = rh * 2 + uj;
            float zi = acc[0 + off]  + bfh(z[0 + rh], uj);
            float zf = acc[4 + off]  + bfh(z[2 + rh], uj);
            float zg = acc[8 + off]  + bfh(z[4 + rh], uj);
            float zo = acc[12 + off] + bfh(z[6 + rh], uj);
            float cc = sigx(zf) * c[off] + sigx(zi) * tanhx(zg);
            c[off] = cc;
            hv[uj] = sigx(zo) * tanhx(cc);
        }
        const int row = RB + rh * 8 + g;
        const int u   = UB + 2 * tg;
        uint32_t pk = packbf2(hv[0], hv[1]);
        asm volatile("st.shared.b32 [%0], %1;"
                     :: "r"(hBase + row * SX_W2 + u * 2), "r"(pk));
    }
}

// load Z1 fragment for timestep t: z[gi*2+rh]
__device__ __forceinline__ void load_z(uint32_t* z, size_t base0, size_t base1, int t) {
    const char* zp = reinterpret_cast<const char*>(g_z1);
#pragma unroll
    for (int gi = 0; gi < 4; gi++) {
        z[gi * 2 + 0] = *reinterpret_cast<const uint32_t*>(
            zp + (base0 + (size_t)t * 256 + gi * 64) * 2);
        z[gi * 2 + 1] = *reinterpret_cast<const uint32_t*>(
            zp + (base1 + (size_t)t * 256 + gi * 64) * 2);
    }
}

// ============================================================
// Recurrent kernel: 16 warps; L1(it+1) + L2(it) per iter; 1 barrier/step
// ============================================================
__global__ void __launch_bounds__(THREADS)
lstm_recurrent(const float* __restrict__ U1, const float* __restrict__ W2,
               const float* __restrict__ U2, const float* __restrict__ b2,
               const float* __restrict__ Wd, const float* __restrict__ bd,
               float* __restrict__ out) {
    extern __shared__ char smem[];
    const uint32_t sb = smem_to_u32(smem);
    const int tid  = threadIdx.x;
    const int wid  = tid >> 5;
    const int lane = tid & 31;
    const int rt = wid >> 3, ug = wid & 7;
    const int RB = rt * 16, UB = ug * 8;

    // zero smem
    for (int i = tid * 16; i < SMEM_TOTAL; i += THREADS * 16)
        *reinterpret_cast<uint4*>(smem + i) = make_uint4(0, 0, 0, 0);
    __syncthreads();

    // stage weights [n][k] bf16 (transposed)
    for (int i = tid; i < 256 * 64; i += THREADS) {       // U1t
        int k = i >> 8, n = i & 255;
        *reinterpret_cast<__nv_bfloat16*>(smem + OFF_U1 + n * SX_U1 + k * 2) =
            __float2bfloat16(U1[k * 256 + n]);
    }
    for (int i = tid; i < 256 * 65; i += THREADS) {       // W2t + b2@k=64
        int k = i / 256, n = i - k * 256;
        float v = (k < 64) ? W2[k * 256 + n] : b2[n];
        *reinterpret_cast<__nv_bfloat16*>(smem + OFF_W2 + n * SX_W2 + k * 2) =
            __float2bfloat16(v);
    }
    for (int i = tid; i < 256 * 64; i += THREADS) {       // U2t
        int k = i >> 8, n = i & 255;
        *reinterpret_cast<__nv_bfloat16*>(smem + OFF_U2 + n * SX_U2 + k * 2) =
            __float2bfloat16(U2[k * 256 + n]);
    }
    if (tid < 64) *reinterpret_cast<float*>(smem + OFF_WD + 4 * tid) = Wd[tid];
    if (tid == 64) *reinterpret_cast<float*>(smem + OFF_BD) = bd[0];
    // ones-column in H1 (both parities) for b2
    if (tid < 2 * ROWS) {
        int b = tid >> 5, r = tid & 31;
        *reinterpret_cast<__nv_bfloat16*>(smem + OFF_H1 + b * ROWS * SX_W2 +
                                          r * SX_W2 + 64 * 2) = __float2bfloat16(1.0f);
    }
    __syncthreads();

    // hoist U2 B-fragments into registers (loop-invariant)
    uint32_t u2b[32];
    {
        const int bq = lane >> 3;
        const int browL = (bq >> 1) * 64 + UB + (lane & 7);
        const int bk = (bq & 1) << 3;
#pragma unroll
        for (int ks = 0; ks < 4; ks++)
#pragma unroll
        for (int gp = 0; gp < 2; gp++)
            ldsm_x4(sb + OFF_U2 + (gp * 128 + browL) * SX_U2 + (ks * 16 + bk) * 2,
                    u2b[(ks * 2 + gp) * 4 + 0], u2b[(ks * 2 + gp) * 4 + 1],
                    u2b[(ks * 2 + gp) * 4 + 2], u2b[(ks * 2 + gp) * 4 + 3]);
    }

    const float* wd_s = reinterpret_cast<const float*>(smem + OFF_WD);
    float* red = reinterpret_cast<float*>(smem + OFF_RED);

    // Z1 fragment base offsets (elements) for this thread
    const int g = lane >> 2, tg = lane & 3;
    const size_t r0 = (size_t)(blockIdx.x * ROWS + RB + g);
    const size_t zb0 = (r0)     * (SEQ * 256) + UB + 2 * tg;
    const size_t zb1 = (r0 + 8) * (SEQ * 256) + UB + 2 * tg;

    float acc1[16], acc2[16], c1[4], c2[4], pr[2] = {0.f, 0.f};
    uint32_t zreg[8];
#pragma unroll
    for (int q = 0; q < 4; q++) { c1[q] = 0.f; c2[q] = 0.f; }

    // ---- prologue: h1(0) = gates(Z1(0)) -> H1[0] ----
    load_z(zreg, zb0, zb1, 0);
#pragma unroll
    for (int q = 0; q < 16; q++) acc1[q] = 0.f;
    epilogue_z(acc1, zreg, c1, sb + OFF_H1, RB, UB, lane);
    __syncthreads();

    // ---- main loop: L1(it+1) + L2(it); one barrier/step ----
    // Buffers at iter it: H1[it&1]=h1(it), H2[(it+1)&1]=h2(it-1)
#pragma unroll 1
    for (int it = 0; it < SEQ; it++) {
        const int pa = it & 1, pb = (it + 1) & 1;
        const bool doL1 = (it < SEQ - 1);
        if (doL1) load_z(zreg, zb0, zb1, it + 1);

#pragma unroll
        for (int q = 0; q < 16; q++) { acc1[q] = 0.f; acc2[q] = 0.f; }

        uint32_t h1A = sb + OFF_H1 + pa * ROWS * SX_W2;
        uint32_t u1B = sb + OFF_U1 + UB * SX_U1;
        uint32_t w2B = sb + OFF_W2 + UB * SX_W2;
        if (doL1) do_fused<true>(h1A, u1B, w2B, RB, acc1, acc2, lane);
        else      do_fused<false>(h1A, u1B, w2B, RB, acc1, acc2, lane);
        do_u2reg(sb + OFF_H2 + pb * ROWS * SX_U2, u2b, RB, acc2, lane);

        if (doL1)
            epilogue_z(acc1, zreg, c1, sb + OFF_H1 + pb * ROWS * SX_W2, RB, UB, lane);
        epilogue(acc2, c2, sb + OFF_H2 + pa * ROWS * SX_U2, SX_U2,
                 RB, UB, lane, (it == SEQ - 1) ? wd_s : nullptr, pr);

        __syncthreads();
    }

    // ---- dense head: out = sigmoid(h2(79) @ Wd + bd) ----
#pragma unroll
    for (int rh = 0; rh < 2; rh++) {
        pr[rh] += __shfl_xor_sync(0xffffffffu, pr[rh], 1);
        pr[rh] += __shfl_xor_sync(0xffffffffu, pr[rh], 2);
    }
    if ((lane & 3) == 0) {
        int gg = lane >> 2;
#pragma unroll
        for (int rh = 0; rh < 2; rh++)
            red[(RB + rh * 8 + gg) * 8 + ug] = pr[rh];
    }
    __syncthreads();
    if (tid < ROWS) {
        float bdv = *reinterpret_cast<const float*>(smem + OFF_BD);
        float v = bdv;
#pragma unroll
        for (int q = 0; q < 8; q++) v += red[tid * 8 + q];
        out[blockIdx.x * ROWS + tid] = sigx(v);
    }
}

// ============================================================
// Launch: precompute Z1, then recurrent kernel
// ============================================================
extern "C" void kernel_launch(void* const* d_in, const int* in_sizes, int n_in,
                              void* d_out, int out_size) {
    const int*   tokens = (const int*)d_in[0];
    const float* emb    = (const float*)d_in[1];
    const float* W1     = (const float*)d_in[2];
    const float* U1     = (const float*)d_in[3];
    const float* b1     = (const float*)d_in[4];
    const float* W2     = (const float*)d_in[5];
    const float* U2     = (const float*)d_in[6];
    const float* b2     = (const float*)d_in[7];
    const float* Wd     = (const float*)d_in[8];
    const float* bd     = (const float*)d_in[9];
    float* out = (float*)d_out;
    (void)b1;

    cudaFuncSetAttribute(precompute_z1,
                         cudaFuncAttributeMaxDynamicSharedMemorySize, P_SMEM);
    cudaFuncSetAttribute(lstm_recurrent,
                         cudaFuncAttributeMaxDynamicSharedMemorySize, SMEM_ALLOC);

    precompute_z1<<<P_GRID, 256, P_SMEM>>>(tokens, emb, W1, d_in[4] ? (const float*)d_in[4] : b1);
    lstm_recurrent<<<NCTA, THREADS, SMEM_ALLOC>>>(U1, W2, U2, b2, Wd, bd, out);
}

// round 16
// speedup vs baseline: 1.1117x; 1.1117x over previous
#include <cuda_runtime.h>
#include <cuda_bf16.h>
#include <cstdint>
#include <cstring>

// ============================================================
// Problem constants
// ============================================================
static constexpr int SEQ   = 80;
static constexpr int EMB   = 100;
static constexpr int BATCH = 4096;
static constexpr int ROWS  = 32;    // batch rows per CTA (recurrent kernel)
static constexpr int NCTA  = 128;   // 4096 / 32
static constexpr int THREADS = 256; // 8 warps, M32 x N32 tiles (ug 0..7)

// Z1 = x@W1 + b1, bf16, gate-interleaved: row m = b*SEQ+t (512B),
// element byte offset = unit*8 + gate*2   (gates i,f,g,o)
__device__ __nv_bfloat16 g_z1[(size_t)BATCH * SEQ * 256];

// ============================================================
// Common helpers
// ============================================================
__device__ __forceinline__ uint32_t smem_to_u32(const void* smem_ptr) {
    uint32_t addr;
    asm("{ .reg .u64 tmp; cvta.to.shared.u64 tmp, %1; cvt.u32.u64 %0, tmp; }"
        : "=r"(addr) : "l"(smem_ptr));
    return addr;
}
__device__ __forceinline__ float tanhx(float x) {
    float y;
    asm("tanh.approx.f32 %0, %1;" : "=f"(y) : "f"(x));
    return y;
}
__device__ __forceinline__ float sigx(float x) {
    return fmaf(tanhx(0.5f * x), 0.5f, 0.5f);
}
__device__ __forceinline__ uint32_t packbf2(float lo, float hi) {
    __nv_bfloat162 v = __floats2bfloat162_rn(lo, hi);
    uint32_t u;
    memcpy(&u, &v, 4);
    return u;
}
__device__ __forceinline__ float bfh(uint32_t u, int hi) {
    return __uint_as_float(hi ? (u & 0xffff0000u) : (u << 16));
}
// f16x2: pack(lo,hi), tanh, unpack
__device__ __forceinline__ uint32_t f16x2pack(float lo, float hi) {
    uint32_t r;
    asm("cvt.rn.f16x2.f32 %0, %1, %2;" : "=r"(r) : "f"(hi), "f"(lo));
    return r;
}
__device__ __forceinline__ uint32_t tanh2(uint32_t x) {
    uint32_t y;
    asm("tanh.approx.f16x2 %0, %1;" : "=r"(y) : "r"(x));
    return y;
}
__device__ __forceinline__ float f16lo(uint32_t h) {
    float f;
    asm("{.reg .b16 l,hh; mov.b32 {l,hh}, %1; cvt.f32.f16 %0, l;}" : "=f"(f) : "r"(h));
    return f;
}
__device__ __forceinline__ float f16hi(uint32_t h) {
    float f;
    asm("{.reg .b16 l,hh; mov.b32 {l,hh}, %1; cvt.f32.f16 %0, hh;}" : "=f"(f) : "r"(h));
    return f;
}
__device__ __forceinline__ void ldsm_x4(uint32_t addr, uint32_t& r0, uint32_t& r1,
                                        uint32_t& r2, uint32_t& r3) {
    asm volatile("ldmatrix.sync.aligned.m8n8.x4.shared.b16 {%0,%1,%2,%3}, [%4];"
                 : "=r"(r0), "=r"(r1), "=r"(r2), "=r"(r3) : "r"(addr));
}
__device__ __forceinline__ void mma16816(float* d, uint32_t a0, uint32_t a1,
                                         uint32_t a2, uint32_t a3,
                                         uint32_t b0, uint32_t b1) {
    asm volatile(
        "mma.sync.aligned.m16n8k16.row.col.f32.bf16.bf16.f32 "
        "{%0,%1,%2,%3}, {%4,%5,%6,%7}, {%8,%9}, {%0,%1,%2,%3};"
        : "+f"(d[0]), "+f"(d[1]), "+f"(d[2]), "+f"(d[3])
        : "r"(a0), "r"(a1), "r"(a2), "r"(a3), "r"(b0), "r"(b1));
}

// Full LSTM gate math for a pair of units, tanh in f16x2 (5 MUFU for 2 units).
// sigma(x) = 0.5 + 0.5*tanh(x/2); c stays fp32.
__device__ __forceinline__ void gate_pair(float zi0, float zi1, float zf0, float zf1,
                                          float zg0, float zg1, float zo0, float zo1,
                                          float& c0, float& c1, float& h0, float& h1) {
    uint32_t ti = tanh2(f16x2pack(0.5f * zi0, 0.5f * zi1));
    uint32_t tf = tanh2(f16x2pack(0.5f * zf0, 0.5f * zf1));
    uint32_t tg = tanh2(f16x2pack(zg0, zg1));
    uint32_t to = tanh2(f16x2pack(0.5f * zo0, 0.5f * zo1));
    float tgl = f16lo(tg), tgh = f16hi(tg);
    c0 = 0.5f * (fmaf(f16lo(tf), c0, c0) + fmaf(f16lo(ti), tgl, tgl));
    c1 = 0.5f * (fmaf(f16hi(tf), c1, c1) + fmaf(f16hi(ti), tgh, tgh));
    uint32_t tc = tanh2(f16x2pack(c0, c1));
    float tcl = f16lo(tc), tch = f16hi(tc);
    h0 = 0.5f * fmaf(f16lo(to), tcl, tcl);
    h1 = 0.5f * fmaf(f16hi(to), tch, tch);
}

// ============================================================
// Precompute kernel: Z1 = (emb[tokens] | 1) @ (W1t | b1), bf16 gate-interleaved
// 296 CTAs x 256 thr (occ 2), pipelined gather, coalesced STG.128 stores
// ============================================================
static constexpr int P_GRID  = 296;
static constexpr int P_TILES = BATCH * SEQ / 32;                 // 10240
static constexpr int P_TPC   = (P_TILES + P_GRID - 1) / P_GRID;  // 35
static constexpr int P_OFF_W = 0;        // W1t [256 n][240B]
static constexpr int P_OFF_A = 61440;    // A   [32 m][240B]
static constexpr int P_SMEM  = 61440 + 32 * 240;  // 69120

// M16 x N64 warp tile: acc[gi*8 + nt*4 + rh*2 + uj]
template <int KSTEPS>
__device__ __forceinline__ void do_term64(uint32_t aBase, int aStride,
                                          uint32_t bBase, int bStride,
                                          int RB, int UB, float* acc, int lane) {
    const int lrow = lane & 15;
    const int lk   = (lane >> 4) << 3;
#pragma unroll
    for (int ks = 0; ks < KSTEPS; ks++) {
        uint32_t a0, a1, a2, a3;
        ldsm_x4(aBase + (RB + lrow) * aStride + (ks * 16 + lk) * 2, a0, a1, a2, a3);
#pragma unroll
        for (int gi = 0; gi < 4; gi++) {
            uint32_t r0, r1, r2, r3;
            ldsm_x4(bBase + (gi * 64 + UB + lrow) * bStride + (ks * 16 + lk) * 2,
                    r0, r1, r2, r3);
            mma16816(acc + gi * 8 + 0, a0, a1, a2, a3, r0, r2);
            mma16816(acc + gi * 8 + 4, a0, a1, a2, a3, r1, r3);
        }
    }
}

__global__ void __launch_bounds__(256, 2)
precompute_z1(const int* __restrict__ tokens, const float* __restrict__ emb,
              const float* __restrict__ W1, const float* __restrict__ b1) {
    extern __shared__ char smem[];
    const uint32_t sb = smem_to_u32(smem);
    const int tid  = threadIdx.x;
    const int wid  = tid >> 5;
    const int lane = tid & 31;
    const int rt = wid >> 2, ug = wid & 3;
    const int RB = rt * 16, UB = ug * 16;

    for (int i = tid * 16; i < P_SMEM; i += 256 * 16)
        *reinterpret_cast<uint4*>(smem + i) = make_uint4(0, 0, 0, 0);
    __syncthreads();
    for (int i = tid; i < 256 * 101; i += 256) {
        int k = i / 256, n = i - k * 256;
        float v = (k < EMB) ? W1[k * 256 + n] : b1[n];
        *reinterpret_cast<__nv_bfloat16*>(smem + P_OFF_W + n * 240 + k * 2) =
            __float2bfloat16(v);
    }
    __syncthreads();

    const int r = tid >> 3, seg = tid & 7;   // 32 rows x 8 threads
    const int g = lane >> 2, tg = lane & 3;

    // prologue gather (tile 0)
    float4 v[4];
    {
        int tile = blockIdx.x * P_TPC;
        if (tile < P_TILES) {
            int tok = tokens[tile * 32 + r];
            const float4* ep = reinterpret_cast<const float4*>(emb + (size_t)tok * EMB);
            v[0] = ep[seg]; v[1] = ep[seg + 8]; v[2] = ep[seg + 16];
            if (seg == 0) v[3] = ep[24];
        }
    }

#pragma unroll 1
    for (int i = 0; i < P_TPC; i++) {
        int tile = blockIdx.x * P_TPC + i;
        if (tile >= P_TILES) break;
        int mBase = tile * 32;

        // store A (from prefetched regs), bf16, ones col at k=100
        {
            uint32_t ab = sb + P_OFF_A + r * 240;
            uint32_t lo, hi;
            lo = packbf2(v[0].x, v[0].y); hi = packbf2(v[0].z, v[0].w);
            asm volatile("st.shared.v2.b32 [%0], {%1,%2};" :: "r"(ab + seg * 8), "r"(lo), "r"(hi));
            lo = packbf2(v[1].x, v[1].y); hi = packbf2(v[1].z, v[1].w);
            asm volatile("st.shared.v2.b32 [%0], {%1,%2};" :: "r"(ab + (seg + 8) * 8), "r"(lo), "r"(hi));
            lo = packbf2(v[2].x, v[2].y); hi = packbf2(v[2].z, v[2].w);
            asm volatile("st.shared.v2.b32 [%0], {%1,%2};" :: "r"(ab + (seg + 16) * 8), "r"(lo), "r"(hi));
            if (seg == 0) {
                lo = packbf2(v[3].x, v[3].y); hi = packbf2(v[3].z, v[3].w);
                asm volatile("st.shared.v2.b32 [%0], {%1,%2};" :: "r"(ab + 192), "r"(lo), "r"(hi));
                unsigned short one = 0x3F80;
                asm volatile("st.shared.b16 [%0], %1;" :: "r"(ab + 200), "h"(one));
            }
        }
        __syncthreads();

        // prefetch next tile's gather (overlaps GEMM)
        if (i + 1 < P_TPC && tile + 1 < P_TILES) {
            int tok = tokens[(tile + 1) * 32 + r];
            const float4* ep = reinterpret_cast<const float4*>(emb + (size_t)tok * EMB);
            v[0] = ep[seg]; v[1] = ep[seg + 8]; v[2] = ep[seg + 16];
            if (seg == 0) v[3] = ep[24];
        }

        float acc[32];
#pragma unroll
        for (int q = 0; q < 32; q++) acc[q] = 0.f;
        do_term64<7>(sb + P_OFF_A, 240, sb + P_OFF_W, 240, RB, UB, acc, lane);

        // store Z gate-interleaved: byte = u*8 + gi*2; 4x STG.128 per thread
        char* zp = reinterpret_cast<char*>(g_z1);
#pragma unroll
        for (int rh = 0; rh < 2; rh++) {
            size_t mrow = (size_t)(mBase + RB + rh * 8 + g) * 512;
#pragma unroll
            for (int nt = 0; nt < 2; nt++) {
                int u0 = UB + nt * 8 + 2 * tg;
                uint4 w;
                w.x = packbf2(acc[0 * 8 + nt * 4 + rh * 2 + 0], acc[1 * 8 + nt * 4 + rh * 2 + 0]);
                w.y = packbf2(acc[2 * 8 + nt * 4 + rh * 2 + 0], acc[3 * 8 + nt * 4 + rh * 2 + 0]);
                w.z = packbf2(acc[0 * 8 + nt * 4 + rh * 2 + 1], acc[1 * 8 + nt * 4 + rh * 2 + 1]);
                w.w = packbf2(acc[2 * 8 + nt * 4 + rh * 2 + 1], acc[3 * 8 + nt * 4 + rh * 2 + 1]);
                *reinterpret_cast<uint4*>(zp + mrow + (size_t)u0 * 8) = w;
            }
        }
        __syncthreads();
    }
}

// ============================================================
// Recurrent kernel smem layout
// ============================================================
static constexpr int SX_U1 = 144;  // k=64
static constexpr int SX_W2 = 176;  // k=80 (h1:64 + bias@64 + pad)
static constexpr int SX_U2 = 144;  // k=64
static constexpr int OFF_U1 = 0;
static constexpr int OFF_W2 = 36864;
static constexpr int OFF_U2 = 81920;
static constexpr int OFF_H1 = 118784;   // 2 x [32][176]
static constexpr int OFF_H2 = 130048;   // 2 x [32][144]
static constexpr int OFF_WD = 139264;   // 64 f32
static constexpr int OFF_BD = 139520;
static constexpr int OFF_RED = 139536;  // [32][8] f32
static constexpr int SMEM_TOTAL = OFF_RED + 1024;  // 140560
static constexpr int SMEM_ALLOC = 140672;

// ============================================================
// Recurrent kernel: 8 warps, warp = M32 x N32 (8 units x 4 gates at UB)
// acc[(m*4+gi)*4 + rh*2 + uj]
// ============================================================
template <bool WITH_U1>
__device__ __forceinline__ void do_fused(uint32_t h1Base, uint32_t u1Base,
                                         uint32_t w2Base, float* acc1, float* acc2,
                                         int lane) {
    const int lrow = lane & 15;
    const int lk   = (lane >> 4) << 3;
    const int bq   = lane >> 3;
    const int brow = (bq >> 1) * 64 + (lane & 7);   // UB folded into bases
    const int bk   = (bq & 1) << 3;
#pragma unroll
    for (int ks = 0; ks < 5; ks++) {
        uint32_t a0, a1, a2, a3, a4, a5, a6, a7;
        ldsm_x4(h1Base + lrow * SX_W2 + (ks * 16 + lk) * 2, a0, a1, a2, a3);
        ldsm_x4(h1Base + (16 + lrow) * SX_W2 + (ks * 16 + lk) * 2, a4, a5, a6, a7);
#pragma unroll
        for (int gp = 0; gp < 2; gp++) {
            uint32_t r0, r1, r2, r3;
            ldsm_x4(w2Base + (gp * 128 + brow) * SX_W2 + (ks * 16 + bk) * 2,
                    r0, r1, r2, r3);
            mma16816(acc2 + (0 * 4 + 2 * gp + 0) * 4, a0, a1, a2, a3, r0, r1);
            mma16816(acc2 + (0 * 4 + 2 * gp + 1) * 4, a0, a1, a2, a3, r2, r3);
            mma16816(acc2 + (1 * 4 + 2 * gp + 0) * 4, a4, a5, a6, a7, r0, r1);
            mma16816(acc2 + (1 * 4 + 2 * gp + 1) * 4, a4, a5, a6, a7, r2, r3);
            if (WITH_U1 && ks < 4) {
                uint32_t s0, s1, s2, s3;
                ldsm_x4(u1Base + (gp * 128 + brow) * SX_U1 + (ks * 16 + bk) * 2,
                        s0, s1, s2, s3);
                mma16816(acc1 + (0 * 4 + 2 * gp + 0) * 4, a0, a1, a2, a3, s0, s1);
                mma16816(acc1 + (0 * 4 + 2 * gp + 1) * 4, a0, a1, a2, a3, s2, s3);
                mma16816(acc1 + (1 * 4 + 2 * gp + 0) * 4, a4, a5, a6, a7, s0, s1);
                mma16816(acc1 + (1 * 4 + 2 * gp + 1) * 4, a4, a5, a6, a7, s2, s3);
            }
        }
    }
}

__device__ __forceinline__ void do_u2reg(uint32_t h2Base, const uint32_t* u2b,
                                         float* acc2, int lane) {
    const int lrow = lane & 15;
    const int lk   = (lane >> 4) << 3;
#pragma unroll
    for (int ks = 0; ks < 4; ks++) {
        uint32_t a0, a1, a2, a3, a4, a5, a6, a7;
        ldsm_x4(h2Base + lrow * SX_U2 + (ks * 16 + lk) * 2, a0, a1, a2, a3);
        ldsm_x4(h2Base + (16 + lrow) * SX_U2 + (ks * 16 + lk) * 2, a4, a5, a6, a7);
#pragma unroll
        for (int gp = 0; gp < 2; gp++) {
            const uint32_t* b = u2b + (ks * 2 + gp) * 4;
            mma16816(acc2 + (0 * 4 + 2 * gp + 0) * 4, a0, a1, a2, a3, b[0], b[1]);
            mma16816(acc2 + (0 * 4 + 2 * gp + 1) * 4, a0, a1, a2, a3, b[2], b[3]);
            mma16816(acc2 + (1 * 4 + 2 * gp + 0) * 4, a4, a5, a6, a7, b[0], b[1]);
            mma16816(acc2 + (1 * 4 + 2 * gp + 1) * 4, a4, a5, a6, a7, b[2], b[3]);
        }
    }
}

// Layer epilogue: 2 m x 2 rh x unit-pair. zq != nullptr adds Z1 preacts.
__device__ __forceinline__ void epi_layer(const float* acc, const uint4* zq,
                                          float* c, uint32_t hBase, int hStride,
                                          int UB, int g, int tg,
                                          const float* wd_s, float* pr) {
#pragma unroll
    for (int m = 0; m < 2; m++)
#pragma unroll
    for (int rh = 0; rh < 2; rh++) {
        const int e0 = rh * 2, e1 = rh * 2 + 1;
        float zi0 = acc[(m * 4 + 0) * 4 + e0], zi1 = acc[(m * 4 + 0) * 4 + e1];
        float zf0 = acc[(m * 4 + 1) * 4 + e0], zf1 = acc[(m * 4 + 1) * 4 + e1];
        float zg0 = acc[(m * 4 + 2) * 4 + e0], zg1 = acc[(m * 4 + 2) * 4 + e1];
        float zo0 = acc[(m * 4 + 3) * 4 + e0], zo1 = acc[(m * 4 + 3) * 4 + e1];
        if (zq) {
            uint4 w = zq[m * 2 + rh];
            zi0 += bfh(w.x, 0); zf0 += bfh(w.x, 1);
            zg0 += bfh(w.y, 0); zo0 += bfh(w.y, 1);
            zi1 += bfh(w.z, 0); zf1 += bfh(w.z, 1);
            zg1 += bfh(w.w, 0); zo1 += bfh(w.w, 1);
        }
        float h0, h1;
        gate_pair(zi0, zi1, zf0, zf1, zg0, zg1, zo0, zo1,
                  c[(m * 2 + rh) * 2 + 0], c[(m * 2 + rh) * 2 + 1], h0, h1);
        const int row = m * 16 + rh * 8 + g;
        const int u   = UB + 2 * tg;
        uint32_t pk = packbf2(h0, h1);
        asm volatile("st.shared.b32 [%0], %1;"
                     :: "r"(hBase + row * hStride + u * 2), "r"(pk));
        if (wd_s) pr[m * 2 + rh] += h0 * wd_s[u] + h1 * wd_s[u + 1];
    }
}

__global__ void __launch_bounds__(THREADS)
lstm_recurrent(const float* __restrict__ U1, const float* __restrict__ W2,
               const float* __restrict__ U2, const float* __restrict__ b2,
               const float* __restrict__ Wd, const float* __restrict__ bd,
               float* __restrict__ out) {
    extern __shared__ char smem[];
    const uint32_t sb = smem_to_u32(smem);
    const int tid  = threadIdx.x;
    const int wid  = tid >> 5;
    const int lane = tid & 31;
    const int ug = wid;            // 8 warps, 8 units each
    const int UB = ug * 8;
    const int g = lane >> 2, tg = lane & 3;

    for (int i = tid * 16; i < SMEM_TOTAL; i += THREADS * 16)
        *reinterpret_cast<uint4*>(smem + i) = make_uint4(0, 0, 0, 0);
    __syncthreads();

    for (int i = tid; i < 256 * 64; i += THREADS) {       // U1t
        int k = i >> 8, n = i & 255;
        *reinterpret_cast<__nv_bfloat16*>(smem + OFF_U1 + n * SX_U1 + k * 2) =
            __float2bfloat16(U1[k * 256 + n]);
    }
    for (int i = tid; i < 256 * 65; i += THREADS) {       // W2t + b2@k=64
        int k = i / 256, n = i - k * 256;
        float v = (k < 64) ? W2[k * 256 + n] : b2[n];
        *reinterpret_cast<__nv_bfloat16*>(smem + OFF_W2 + n * SX_W2 + k * 2) =
            __float2bfloat16(v);
    }
    for (int i = tid; i < 256 * 64; i += THREADS) {       // U2t
        int k = i >> 8, n = i & 255;
        *reinterpret_cast<__nv_bfloat16*>(smem + OFF_U2 + n * SX_U2 + k * 2) =
            __float2bfloat16(U2[k * 256 + n]);
    }
    if (tid < 64) *reinterpret_cast<float*>(smem + OFF_WD + 4 * tid) = Wd[tid];
    if (tid == 64) *reinterpret_cast<float*>(smem + OFF_BD) = bd[0];
    if (tid < 2 * ROWS) {   // ones col in H1 both parities (b2 via ones)
        int b = tid >> 5, r = tid & 31;
        *reinterpret_cast<__nv_bfloat16*>(smem + OFF_H1 + b * ROWS * SX_W2 +
                                          r * SX_W2 + 64 * 2) = __float2bfloat16(1.0f);
    }
    __syncthreads();

    // hoist U2 B-fragments (loop-invariant, 32 regs)
    uint32_t u2b[32];
    {
        const int bq = lane >> 3;
        const int brow = (bq >> 1) * 64 + UB + (lane & 7);
        const int bk = (bq & 1) << 3;
#pragma unroll
        for (int ks = 0; ks < 4; ks++)
#pragma unroll
        for (int gp = 0; gp < 2; gp++)
            ldsm_x4(sb + OFF_U2 + (gp * 128 + brow) * SX_U2 + (ks * 16 + bk) * 2,
                    u2b[(ks * 2 + gp) * 4 + 0], u2b[(ks * 2 + gp) * 4 + 1],
                    u2b[(ks * 2 + gp) * 4 + 2], u2b[(ks * 2 + gp) * 4 + 3]);
    }

    const float* wd_s = reinterpret_cast<const float*>(smem + OFF_WD);
    float* red = reinterpret_cast<float*>(smem + OFF_RED);

    // Z1 per-thread base byte offsets for the 4 (m,rh) rows
    const char* zp = reinterpret_cast<const char*>(g_z1);
    size_t zbase[4];
#pragma unroll
    for (int m = 0; m < 2; m++)
#pragma unroll
    for (int rh = 0; rh < 2; rh++)
        zbase[m * 2 + rh] =
            ((size_t)(blockIdx.x * ROWS + m * 16 + rh * 8 + g) * SEQ) * 512 +
            (size_t)(UB + 2 * tg) * 8;

    float acc1[32], acc2[32], c1[8], c2[8], pr[4] = {0.f, 0.f, 0.f, 0.f};
    uint4 zq[4];
#pragma unroll
    for (int q = 0; q < 8; q++) { c1[q] = 0.f; c2[q] = 0.f; }

    // ---- prologue: h1(0) = gates(Z1(0)) -> H1[0] ----
#pragma unroll
    for (int q = 0; q < 4; q++)
        zq[q] = *reinterpret_cast<const uint4*>(zp + zbase[q]);
#pragma unroll
    for (int q = 0; q < 32; q++) acc1[q] = 0.f;
    epi_layer(acc1, zq, c1, sb + OFF_H1, SX_W2, UB, g, tg, nullptr, pr);
    __syncthreads();

    // ---- main loop: L1(it+1) + L2(it); one barrier/step ----
    // Buffers at iter it: H1[it&1]=h1(it), H2[(it+1)&1]=h2(it-1)
#pragma unroll 1
    for (int it = 0; it < SEQ; it++) {
        const int pa = it & 1, pb = (it + 1) & 1;
        const bool doL1 = (it < SEQ - 1);
        if (doL1) {
#pragma unroll
            for (int q = 0; q < 4; q++)
                zq[q] = *reinterpret_cast<const uint4*>(
                    zp + zbase[q] + (size_t)(it + 1) * 512);
        }
#pragma unroll
        for (int q = 0; q < 32; q++) { acc1[q] = 0.f; acc2[q] = 0.f; }

        uint32_t h1A = sb + OFF_H1 + pa * ROWS * SX_W2;
        uint32_t u1B = sb + OFF_U1 + UB * SX_U1;
        uint32_t w2B = sb + OFF_W2 + UB * SX_W2;
        if (doL1) do_fused<true>(h1A, u1B, w2B, acc1, acc2, lane);
        else      do_fused<false>(h1A, u1B, w2B, acc1, acc2, lane);
        do_u2reg(sb + OFF_H2 + pb * ROWS * SX_U2, u2b, acc2, lane);

        if (doL1)
            epi_layer(acc1, zq, c1, sb + OFF_H1 + pb * ROWS * SX_W2, SX_W2,
                      UB, g, tg, nullptr, pr);
        epi_layer(acc2, nullptr, c2, sb + OFF_H2 + pa * ROWS * SX_U2, SX_U2,
                  UB, g, tg, (it == SEQ - 1) ? wd_s : nullptr, pr);

        __syncthreads();
    }

    // ---- dense head: out = sigmoid(h2(79) @ Wd + bd) ----
#pragma unroll
    for (int q = 0; q < 4; q++) {
        pr[q] += __shfl_xor_sync(0xffffffffu, pr[q], 1);
        pr[q] += __shfl_xor_sync(0xffffffffu, pr[q], 2);
    }
    if (tg == 0) {
#pragma unroll
        for (int m = 0; m < 2; m++)
#pragma unroll
        for (int rh = 0; rh < 2; rh++)
            red[(m * 16 + rh * 8 + g) * 8 + ug] = pr[m * 2 + rh];
    }
    __syncthreads();
    if (tid < ROWS) {
        float bdv = *reinterpret_cast<const float*>(smem + OFF_BD);
        float v = bdv;
#pragma unroll
        for (int q = 0; q < 8; q++) v += red[tid * 8 + q];
        out[blockIdx.x * ROWS + tid] = sigx(v);
    }
}

// ============================================================
// Launch: precompute Z1, then recurrent kernel
// ============================================================
extern "C" void kernel_launch(void* const* d_in, const int* in_sizes, int n_in,
                              void* d_out, int out_size) {
    const int*   tokens = (const int*)d_in[0];
    const float* emb    = (const float*)d_in[1];
    const float* W1     = (const float*)d_in[2];
    const float* U1     = (const float*)d_in[3];
    const float* b1     = (const float*)d_in[4];
    const float* W2     = (const float*)d_in[5];
    const float* U2     = (const float*)d_in[6];
    const float* b2     = (const float*)d_in[7];
    const float* Wd     = (const float*)d_in[8];
    const float* bd     = (const float*)d_in[9];
    float* out = (float*)d_out;

    cudaFuncSetAttribute(precompute_z1,
                         cudaFuncAttributeMaxDynamicSharedMemorySize, P_SMEM);
    cudaFuncSetAttribute(lstm_recurrent,
                         cudaFuncAttributeMaxDynamicSharedMemorySize, SMEM_ALLOC);

    precompute_z1<<<P_GRID, 256, P_SMEM>>>(tokens, emb, W1, b1);
    lstm_recurrent<<<NCTA, 256, SMEM_ALLOC>>>(U1, W2, U2, b2, Wd, bd, out);
}